// round 17
// baseline (speedup 1.0000x reference)
#include <cuda_runtime.h>
#include <cstdint>
#include <cstddef>

#define MAXN 10000
#define MAXE 160000
#define NSM  148

__device__ float g_x0[MAXN * 16];
__device__ float g_x1[MAXN * 12];
__device__ float g_qd0[MAXN * 8];
__device__ float g_qd1[MAXN * 6];
__device__ float g_logit[MAXE];
__device__ float g_m[MAXN];
__device__ float g_z[MAXN];
__device__ float g_agg[MAXN * 28];     // AoS
__device__ float g_h2k[(size_t)MAXE * 64];   // TRANSPOSED [c*E+e], pre-tf32
__device__ float g_h2v[(size_t)MAXE * 64];   // TRANSPOSED [c*E+e], pre-tf32
__device__ float g_eg[(size_t)MAXE * 32];    // SoA: 0-15 xl0, 16-19 ul1, 20-31 xl1
__device__ float g_qg[(size_t)MAXE * 14];    // SoA: 0-7 qd0[dst], 8-13 qd1[dst]

__device__ __forceinline__ float frelu(float x) { return x > 0.f ? x : 0.f; }

__device__ __forceinline__ void atomicMaxF(float* addr, float v) {
    if (v >= 0.f) atomicMax((int*)addr, __float_as_int(v));
    else          atomicMin((unsigned int*)addr, __float_as_uint(v));
}

// ---- tf32 helpers ----------------------------------------------------------
__device__ __forceinline__ float to_tf32(float x) {
    uint32_t u; asm("cvt.rna.tf32.f32 %0, %1;" : "=r"(u) : "f"(x));
    return __uint_as_float(u);
}
__device__ __forceinline__ void mma_tf32(float* d, const uint32_t* a,
                                         const uint32_t* b) {
    asm volatile(
        "mma.sync.aligned.m16n8k8.row.col.f32.tf32.tf32.f32 "
        "{%0,%1,%2,%3}, {%4,%5,%6,%7}, {%8,%9}, {%0,%1,%2,%3};\n"
        : "+f"(d[0]), "+f"(d[1]), "+f"(d[2]), "+f"(d[3])
        : "r"(a[0]), "r"(a[1]), "r"(a[2]), "r"(a[3]), "r"(b[0]), "r"(b[1]));
}

// ---------------------------------------------------------------------------
// Kernel A: node prep (+ fused init of g_agg / g_m / g_z)
// ---------------------------------------------------------------------------
__global__ void node_prep_kernel(const float* __restrict__ na,
                                 const float* __restrict__ Win0,
                                 const float* __restrict__ Win1,
                                 const float* __restrict__ Wq0,
                                 const float* __restrict__ Wq1,
                                 const float* __restrict__ Wd0,
                                 const float* __restrict__ Wd1,
                                 int N) {
    __shared__ float sWin0[512], sWin1[32], sWq0[128], sWq1[8], sWd0[64], sWd1[4];
    int tid = threadIdx.x;
    // fused init (grid-stride)
    for (int i = blockIdx.x * blockDim.x + tid; i < N * 28;
         i += gridDim.x * blockDim.x)
        g_agg[i] = 0.f;

    for (int i = tid; i < 512; i += blockDim.x) sWin0[i] = Win0[i];
    for (int i = tid; i < 32;  i += blockDim.x) sWin1[i] = Win1[i];
    for (int i = tid; i < 128; i += blockDim.x) sWq0[i]  = Wq0[i];
    for (int i = tid; i < 8;   i += blockDim.x) sWq1[i]  = Wq1[i];
    for (int i = tid; i < 64;  i += blockDim.x) sWd0[i]  = Wd0[i];
    for (int i = tid; i < 4;   i += blockDim.x) sWd1[i]  = Wd1[i];
    __syncthreads();

    int n = blockIdx.x * blockDim.x + tid;
    if (n >= N) return;
    g_m[n] = __int_as_float(0xff800000);  // -inf
    g_z[n] = 0.f;

    const float* p = na + (size_t)n * 56;
    float a0[32], a1[24];
#pragma unroll
    for (int i = 0; i < 32; i++) a0[i] = p[i];
#pragma unroll
    for (int i = 0; i < 24; i++) a1[i] = p[32 + i];

    float x0[16];
#pragma unroll
    for (int o = 0; o < 16; o++) {
        float s = 0.f;
#pragma unroll
        for (int i = 0; i < 32; i++) s = fmaf(a0[i], sWin0[i * 16 + o], s);
        x0[o] = s * 0.17677669529663687f;   // 1/sqrt(32)
    }
    float x1[12];
#pragma unroll
    for (int o = 0; o < 4; o++)
#pragma unroll
        for (int c = 0; c < 3; c++) {
            float s = 0.f;
#pragma unroll
            for (int m = 0; m < 8; m++) s = fmaf(a1[m * 3 + c], sWin1[m * 4 + o], s);
            x1[o * 3 + c] = s * 0.35355339059327373f;  // 1/sqrt(8)
        }

    float q0[8];
#pragma unroll
    for (int b = 0; b < 8; b++) {
        float s = 0.f;
#pragma unroll
        for (int o = 0; o < 16; o++) s = fmaf(x0[o], sWq0[o * 8 + b], s);
        q0[b] = s * 0.25f;                   // 1/sqrt(16)
    }
    float q1[6];
#pragma unroll
    for (int j = 0; j < 2; j++)
#pragma unroll
        for (int c = 0; c < 3; c++) {
            float s = 0.f;
#pragma unroll
            for (int o = 0; o < 4; o++) s = fmaf(x1[o * 3 + c], sWq1[o * 2 + j], s);
            q1[j * 3 + c] = s * 0.5f;        // 1/sqrt(4)
        }

#pragma unroll
    for (int j = 0; j < 8; j++) {
        float s = 0.f;
#pragma unroll
        for (int i = 0; i < 8; i++) s = fmaf(q0[i], sWd0[i * 8 + j], s);
        g_qd0[(size_t)n * 8 + j] = s;
    }
#pragma unroll
    for (int j = 0; j < 2; j++)
#pragma unroll
        for (int c = 0; c < 3; c++) {
            float s = 0.f;
#pragma unroll
            for (int i = 0; i < 2; i++) s = fmaf(q1[i * 3 + c], sWd1[i * 2 + j], s);
            g_qd1[(size_t)n * 6 + j * 3 + c] = s;
        }

#pragma unroll
    for (int o = 0; o < 16; o++) g_x0[(size_t)n * 16 + o] = x0[o];
#pragma unroll
    for (int o = 0; o < 12; o++) g_x1[(size_t)n * 12 + o] = x1[o];
}

// ---------------------------------------------------------------------------
// FRONT kernel (tensor-core): both MLPs 32->64->64, tiles of 256 edges,
// 512 threads, 1 CTA/SM. Per-tile edge gather fused in (threads < 256).
// smem floats: B1K[32][68] B2K[64][68] B1V B2V | biases | A0[32][260] A1[64][260]
// ---------------------------------------------------------------------------
#define FT_TE  256
#define FT_BP  68
#define FT_AP  260
#define FT_B1K 0
#define FT_B2K 2176
#define FT_B1V 6528
#define FT_B2V 8704
#define FT_b1K 13056
#define FT_b2K 13120
#define FT_b1V 13184
#define FT_b2V 13248
#define FT_A0  13312
#define FT_A1  21632
#define FT_FLOATS 38272

template <int KSTEPS, int MODE>
__device__ __forceinline__ void ft_gemm(const float* __restrict__ As,
                                        const float* __restrict__ Bs,
                                        const float* __restrict__ bias,
                                        float* __restrict__ dst,
                                        int tid, int e0t, int E) {
    int warp = tid >> 5, lane = tid & 31;
    int g = lane >> 2, tc = lane & 3;
    int e0 = warp * 16;

    float acc[8][4];
#pragma unroll
    for (int n = 0; n < 8; n++)
#pragma unroll
        for (int i = 0; i < 4; i++) acc[n][i] = 0.f;

#pragma unroll
    for (int ks = 0; ks < KSTEPS; ks++) {
        int k0 = ks * 8;
        uint32_t a[4];
        a[0] = __float_as_uint(As[(k0 + tc)     * FT_AP + e0 + g]);
        a[1] = __float_as_uint(As[(k0 + tc)     * FT_AP + e0 + g + 8]);
        a[2] = __float_as_uint(As[(k0 + tc + 4) * FT_AP + e0 + g]);
        a[3] = __float_as_uint(As[(k0 + tc + 4) * FT_AP + e0 + g + 8]);
#pragma unroll
        for (int n = 0; n < 8; n++) {
            uint32_t b[2];
            b[0] = __float_as_uint(Bs[(k0 + tc)     * FT_BP + n * 8 + g]);
            b[1] = __float_as_uint(Bs[(k0 + tc + 4) * FT_BP + n * 8 + g]);
            mma_tf32(acc[n], a, b);
        }
    }
#pragma unroll
    for (int n = 0; n < 8; n++) {
        int w0 = n * 8 + 2 * tc;
        float b0 = bias[w0], b1 = bias[w0 + 1];
        float v00 = to_tf32(frelu(b0 + acc[n][0]));
        float v10 = to_tf32(frelu(b1 + acc[n][1]));
        float v01 = to_tf32(frelu(b0 + acc[n][2]));
        float v11 = to_tf32(frelu(b1 + acc[n][3]));
        if (MODE == 0) {
            dst[w0 * FT_AP + e0 + g]           = v00;
            dst[(w0 + 1) * FT_AP + e0 + g]     = v10;
            dst[w0 * FT_AP + e0 + g + 8]       = v01;
            dst[(w0 + 1) * FT_AP + e0 + g + 8] = v11;
        } else {
            int ea = e0t + e0 + g;
            int eb = ea + 8;
            if (ea < E) {
                dst[(size_t)w0 * E + ea]       = v00;
                dst[(size_t)(w0 + 1) * E + ea] = v10;
            }
            if (eb < E) {
                dst[(size_t)w0 * E + eb]       = v01;
                dst[(size_t)(w0 + 1) * E + eb] = v11;
            }
        }
    }
}

__global__ void __launch_bounds__(512, 1)
front_kernel(const float* __restrict__ edge_attr,
             const float* __restrict__ edge_sh,
             const int*   __restrict__ eidx,
             const float* __restrict__ fcW1, const float* __restrict__ fcb1,
             const float* __restrict__ fcW2, const float* __restrict__ fcb2,
             const float* __restrict__ fkW1, const float* __restrict__ fkb1,
             const float* __restrict__ fkW2, const float* __restrict__ fkb2,
             int E, int tiles) {
    extern __shared__ float sm[];
    int tid = threadIdx.x;

    for (int i = tid; i < 32 * FT_BP; i += 512) {
        int c = i / FT_BP, o = i % FT_BP;
        sm[FT_B1K + i] = (o < 64) ? to_tf32(fkW1[c * 64 + o]) : 0.f;
        sm[FT_B1V + i] = (o < 64) ? to_tf32(fcW1[c * 64 + o]) : 0.f;
    }
    for (int i = tid; i < 64 * FT_BP; i += 512) {
        int c = i / FT_BP, o = i % FT_BP;
        sm[FT_B2K + i] = (o < 64) ? to_tf32(fkW2[c * 64 + o]) : 0.f;
        sm[FT_B2V + i] = (o < 64) ? to_tf32(fcW2[c * 64 + o]) : 0.f;
    }
    for (int i = tid; i < 64; i += 512) {
        sm[FT_b1K + i] = fkb1[i];
        sm[FT_b2K + i] = fkb2[i];
        sm[FT_b1V + i] = fcb1[i];
        sm[FT_b2V + i] = fcb2[i];
    }
    __syncthreads();

    for (int tile = blockIdx.x; tile < tiles; tile += gridDim.x) {
        int e0t = tile * FT_TE;
        // fused edge gather: one edge per thread (tid < 256)
        if (tid < FT_TE) {
            int e = e0t + tid;
            if (e < E) {
                int s = eidx[e], d = eidx[E + e];
                float4 sh = reinterpret_cast<const float4*>(edge_sh)[e];
                const float4* x0p =
                    reinterpret_cast<const float4*>(g_x0 + (size_t)s * 16);
                float4 v0 = x0p[0], v1 = x0p[1], v2 = x0p[2], v3 = x0p[3];
                float xl0[16] = {v0.x, v0.y, v0.z, v0.w, v1.x, v1.y, v1.z, v1.w,
                                 v2.x, v2.y, v2.z, v2.w, v3.x, v3.y, v3.z, v3.w};
#pragma unroll
                for (int o = 0; o < 16; o++) g_eg[(size_t)o * E + e] = xl0[o];
                const float4* x1p =
                    reinterpret_cast<const float4*>(g_x1 + (size_t)s * 12);
                float4 w0 = x1p[0], w1 = x1p[1], w2 = x1p[2];
                float x1v[12] = {w0.x, w0.y, w0.z, w0.w, w1.x, w1.y, w1.z, w1.w,
                                 w2.x, w2.y, w2.z, w2.w};
#pragma unroll
                for (int o = 0; o < 12; o++)
                    g_eg[(size_t)(20 + o) * E + e] = x1v[o];
#pragma unroll
                for (int j = 0; j < 4; j++)
                    g_eg[(size_t)(16 + j) * E + e] =
                        x1v[j * 3] * sh.y + x1v[j * 3 + 1] * sh.z +
                        x1v[j * 3 + 2] * sh.w;
                const float4* q0p =
                    reinterpret_cast<const float4*>(g_qd0 + (size_t)d * 8);
                float4 u0 = q0p[0], u1 = q0p[1];
                float qd0[8] = {u0.x, u0.y, u0.z, u0.w, u1.x, u1.y, u1.z, u1.w};
#pragma unroll
                for (int j = 0; j < 8; j++) g_qg[(size_t)j * E + e] = qd0[j];
                const float2* q1p =
                    reinterpret_cast<const float2*>(g_qd1 + (size_t)d * 6);
                float2 t0 = q1p[0], t1 = q1p[1], t2 = q1p[2];
                float qd1[6] = {t0.x, t0.y, t1.x, t1.y, t2.x, t2.y};
#pragma unroll
                for (int j = 0; j < 6; j++)
                    g_qg[(size_t)(8 + j) * E + e] = qd1[j];
            }
        }
        // load A0: transpose edge_attr[e][c] -> A0[c][e], tf32
        for (int i = tid; i < FT_TE * 8; i += 512) {
            int e = i >> 3, q8 = i & 7;
            float4 v;
            if (e0t + e < E)
                v = *reinterpret_cast<const float4*>(
                        edge_attr + (size_t)(e0t + e) * 32 + 4 * q8);
            else { v.x = v.y = v.z = v.w = 0.f; }
            sm[FT_A0 + (4 * q8 + 0) * FT_AP + e] = to_tf32(v.x);
            sm[FT_A0 + (4 * q8 + 1) * FT_AP + e] = to_tf32(v.y);
            sm[FT_A0 + (4 * q8 + 2) * FT_AP + e] = to_tf32(v.z);
            sm[FT_A0 + (4 * q8 + 3) * FT_AP + e] = to_tf32(v.w);
        }
        __syncthreads();
        ft_gemm<4, 0>(sm + FT_A0, sm + FT_B1K, sm + FT_b1K, sm + FT_A1, tid, 0, 0);
        __syncthreads();
        ft_gemm<8, 1>(sm + FT_A1, sm + FT_B2K, sm + FT_b2K, g_h2k, tid, e0t, E);
        __syncthreads();
        ft_gemm<4, 0>(sm + FT_A0, sm + FT_B1V, sm + FT_b1V, sm + FT_A1, tid, 0, 0);
        __syncthreads();
        ft_gemm<8, 1>(sm + FT_A1, sm + FT_B2V, sm + FT_b2V, g_h2v, tid, e0t, E);
        __syncthreads();   // protect A0/A1 before next tile
    }
}

// ---------------------------------------------------------------------------
// L3 tensor-core GEMM machinery (persistent tiles of 128 edges, 512 threads)
// B stored as interleaved (k, k+4) float2 pairs: one LDS.64 per (n, k-step).
//   Bp[kb][tc][w] = { tf32(W[kb*8+tc][w]), tf32(W[kb*8+tc+4][w]) }
// smem floats: Bp 8*1808 | A 64*132 | C 224*132 | bias 224
// ---------------------------------------------------------------------------
#define TE     128
#define NWP    224
#define APAD   132
#define CPAD   132
#define BP2    452      // floats per tc-row (2*224 + 4 pad)
#define BK1    1808     // 4*BP2
#define L3_B_OFF    0
#define L3_A_OFF    14464
#define L3_C_OFF    22912
#define L3_BIAS_OFF 52480
#define L3_FLOATS   52704
#define L3_NT  512

__device__ __forceinline__ void l3_load_A(float* __restrict__ As,
                                          const float* __restrict__ gh2T,
                                          int e0, int E, int tid) {
    for (int i = tid; i < 64 * (TE / 4); i += L3_NT) {
        int c = i >> 5;
        int v = i & 31;
        int eb = e0 + 4 * v;
        float4 f;
        if (eb + 3 < E) {
            f = *reinterpret_cast<const float4*>(gh2T + (size_t)c * E + eb);
        } else {
            f.x = (eb + 0 < E) ? gh2T[(size_t)c * E + eb + 0] : 0.f;
            f.y = (eb + 1 < E) ? gh2T[(size_t)c * E + eb + 1] : 0.f;
            f.z = (eb + 2 < E) ? gh2T[(size_t)c * E + eb + 2] : 0.f;
            f.w = (eb + 3 < E) ? gh2T[(size_t)c * E + eb + 3] : 0.f;
        }
        *reinterpret_cast<float4*>(As + c * APAD + 4 * v) = f;
    }
}

// stage W3 (ld = row stride of source, 200 valid cols padded to 224) into Bp
template <typename F>
__device__ __forceinline__ void l3_load_B(float* __restrict__ Bs, F getw,
                                          int tid) {
    for (int i = tid; i < 8 * 4 * NWP; i += L3_NT) {
        int kb = i / (4 * NWP);
        int r  = i % (4 * NWP);
        int tc = r / NWP;
        int w  = r % NWP;
        float lo = getw(kb * 8 + tc, w);
        float hi = getw(kb * 8 + tc + 4, w);
        Bs[kb * BK1 + tc * BP2 + 2 * w]     = lo;
        Bs[kb * BK1 + tc * BP2 + 2 * w + 1] = hi;
    }
}

__device__ __forceinline__ void l3_gemm_mma(const float* __restrict__ As,
                                            const float* __restrict__ Bs,
                                            float* __restrict__ Cs, int tid) {
    int warp = tid >> 5, lane = tid & 31;
    int g = lane >> 2, tc = lane & 3;
    int wg = warp >> 3;
    int e0 = (warp & 7) * 16;
    int n0 = wg * 14;

    float acc[14][4];
#pragma unroll
    for (int n = 0; n < 14; n++)
#pragma unroll
        for (int i = 0; i < 4; i++) acc[n][i] = 0.f;

#pragma unroll
    for (int kb = 0; kb < 8; kb++) {
        int k0 = kb * 8;
        uint32_t a[4];
        a[0] = __float_as_uint(As[(k0 + tc)     * APAD + e0 + g]);
        a[1] = __float_as_uint(As[(k0 + tc)     * APAD + e0 + g + 8]);
        a[2] = __float_as_uint(As[(k0 + tc + 4) * APAD + e0 + g]);
        a[3] = __float_as_uint(As[(k0 + tc + 4) * APAD + e0 + g + 8]);
        const float2* bp =
            reinterpret_cast<const float2*>(Bs + kb * BK1 + tc * BP2);
#pragma unroll
        for (int n = 0; n < 14; n++) {
            float2 b2 = bp[(n0 + n) * 8 + g];
            uint32_t b[2];
            b[0] = __float_as_uint(b2.x);
            b[1] = __float_as_uint(b2.y);
            mma_tf32(acc[n], a, b);
        }
    }
#pragma unroll
    for (int n = 0; n < 14; n++) {
        int w0 = (n0 + n) * 8 + 2 * tc;
        Cs[w0 * CPAD + e0 + g]           = acc[n][0];
        Cs[(w0 + 1) * CPAD + e0 + g]     = acc[n][1];
        Cs[w0 * CPAD + e0 + g + 8]       = acc[n][2];
        Cs[(w0 + 1) * CPAD + e0 + g + 8] = acc[n][3];
    }
}

// ---------------------------------------------------------------------------
// L3K: persistent tensor GEMM + K contraction + logit (4 threads/edge)
// ---------------------------------------------------------------------------
__global__ void __launch_bounds__(L3_NT, 1)
l3k_kernel(const int* __restrict__ eidx,
           const float* __restrict__ edge_sh,
           const float* __restrict__ fkW3, const float* __restrict__ fkb3,
           int E, int tiles) {
    extern __shared__ float smx[];
    float* Bs  = smx + L3_B_OFF;
    float* As  = smx + L3_A_OFF;
    float* Cs  = smx + L3_C_OFF;
    float* sB3 = smx + L3_BIAS_OFF;
    int tid = threadIdx.x;

    l3_load_B(Bs, [&](int c, int w) {
        return (w < 200) ? to_tf32(fkW3[c * 200 + w]) : 0.f;
    }, tid);
    for (int i = tid; i < NWP; i += L3_NT)
        sB3[i] = (i < 200) ? fkb3[i] : 0.f;

    const float NORM = 0.22360679774997896f;  // 1/sqrt(20)
    const float I3   = 0.5773502691896258f;   // 1/sqrt(3)

    for (int tile = blockIdx.x; tile < tiles; tile += gridDim.x) {
        int e0 = tile * TE;
        l3_load_A(As, g_h2k, e0, E, tid);
        __syncthreads();
        l3_gemm_mma(As, Bs, Cs, tid);
        __syncthreads();

        {
            int el = tid >> 2;
            int h  = tid & 3;
            int e  = e0 + el;
            int ee = (e < E) ? e : (E - 1);
            int d = eidx[E + ee];
            float4 sh = reinterpret_cast<const float4*>(edge_sh)[ee];

            float xl0[16], ul1[4];
#pragma unroll
            for (int o = 0; o < 16; o++) xl0[o] = g_eg[(size_t)o * E + ee];
#pragma unroll
            for (int j = 0; j < 4; j++) ul1[j] = g_eg[(size_t)(16 + j) * E + ee];

            float logit = 0.f;
#pragma unroll
            for (int bb = 0; bb < 2; bb++) {
                int b = 2 * h + bb;
                float acc0 = 0.f;
#pragma unroll
                for (int a = 0; a < 16; a++) {
                    int r = a * 8 + b;
                    acc0 = fmaf(xl0[a], Cs[r * CPAD + el] + sB3[r], acc0);
                }
                float acc1 = 0.f;
#pragma unroll
                for (int a = 0; a < 4; a++) {
                    int r = 168 + a * 8 + b;
                    acc1 = fmaf(ul1[a], Cs[r * CPAD + el] + sB3[r], acc1);
                }
                float k0b = NORM * fmaf(sh.x, acc0, I3 * acc1);
                logit = fmaf(g_qg[(size_t)b * E + ee], k0b, logit);
            }
            if (h < 2) {
                int j = h;
                float c01 = 0.f;
#pragma unroll
                for (int a = 0; a < 16; a++) {
                    int r = 128 + a * 2 + j;
                    c01 = fmaf(xl0[a], Cs[r * CPAD + el] + sB3[r], c01);
                }
                float dx = 0.f, dy = 0.f, dz = 0.f;
#pragma unroll
                for (int a = 0; a < 4; a++) {
                    int r = 160 + a * 2 + j;
                    float w = Cs[r * CPAD + el] + sB3[r];
                    dx = fmaf(g_eg[(size_t)(20 + a * 3 + 0) * E + ee], w, dx);
                    dy = fmaf(g_eg[(size_t)(20 + a * 3 + 1) * E + ee], w, dy);
                    dz = fmaf(g_eg[(size_t)(20 + a * 3 + 2) * E + ee], w, dz);
                }
                float k1x = NORM * (sh.y * c01 + sh.x * dx);
                float k1y = NORM * (sh.z * c01 + sh.x * dy);
                float k1z = NORM * (sh.w * c01 + sh.x * dz);
                logit += I3 * (g_qg[(size_t)(8 + j * 3 + 0) * E + ee] * k1x +
                               g_qg[(size_t)(8 + j * 3 + 1) * E + ee] * k1y +
                               g_qg[(size_t)(8 + j * 3 + 2) * E + ee] * k1z);
            }
            logit += __shfl_xor_sync(0xffffffffu, logit, 1);
            logit += __shfl_xor_sync(0xffffffffu, logit, 2);
            logit *= 0.31622776601683794f;  // 1/sqrt(10)
            if (h == 0 && e < E) {
                g_logit[e] = logit;
                atomicMaxF(&g_m[d], logit);
            }
        }
        __syncthreads();
    }
}

// ---------------------------------------------------------------------------
// L3V (HALF = 0/1): tensor GEMM + V contraction + FUSED softmax-aggregate.
// ---------------------------------------------------------------------------
template <int HALF>
__device__ __forceinline__ int v_wi(int r) {
    if (r < 128) { int a = r >> 3, b = r & 7;        return a * 16 + HALF * 8 + b; }
    if (r < 160) { int t = r - 128; int a = t >> 1;  return 256 + a * 4 + HALF * 2 + (t & 1); }
    if (r < 168) { int t = r - 160; int a = t >> 1;  return 320 + a * 4 + HALF * 2 + (t & 1); }
    { int t = r - 168; int a = t >> 3, b = t & 7;    return 336 + a * 16 + HALF * 8 + b; }
}

template <int HALF>
__global__ void __launch_bounds__(L3_NT, 1)
l3v_kernel(const int* __restrict__ eidx,
           const float* __restrict__ edge_sh,
           const float* __restrict__ fcW3, const float* __restrict__ fcb3,
           int E, int tiles) {
    extern __shared__ float smx[];
    float* Bs  = smx + L3_B_OFF;
    float* As  = smx + L3_A_OFF;
    float* Cs  = smx + L3_C_OFF;
    float* sB3 = smx + L3_BIAS_OFF;
    int tid = threadIdx.x;

    l3_load_B(Bs, [&](int c, int w) {
        return (w < 200) ? to_tf32(fcW3[c * 400 + v_wi<HALF>(w)]) : 0.f;
    }, tid);
    for (int i = tid; i < NWP; i += L3_NT)
        sB3[i] = (i < 200) ? fcb3[v_wi<HALF>(i)] : 0.f;

    const float NORM = 0.22360679774997896f;  // 1/sqrt(20)
    const float I3   = 0.5773502691896258f;   // 1/sqrt(3)

    for (int tile = blockIdx.x; tile < tiles; tile += gridDim.x) {
        int e0 = tile * TE;
        l3_load_A(As, g_h2v, e0, E, tid);
        __syncthreads();
        l3_gemm_mma(As, Bs, Cs, tid);
        __syncthreads();

        {
            int el = tid >> 2;
            int h  = tid & 3;
            int e  = e0 + el;
            bool ok = e < E;
            int ee = ok ? e : (E - 1);
            int d = eidx[E + ee];
            float4 sh = reinterpret_cast<const float4*>(edge_sh)[ee];
            float p = __expf(g_logit[ee] - g_m[d]);

            float xl0[16], ul1[4];
#pragma unroll
            for (int o = 0; o < 16; o++) xl0[o] = g_eg[(size_t)o * E + ee];
#pragma unroll
            for (int j = 0; j < 4; j++) ul1[j] = g_eg[(size_t)(16 + j) * E + ee];

#pragma unroll
            for (int bb = 0; bb < 2; bb++) {
                int b = 2 * h + bb;
                float acc0 = 0.f;
#pragma unroll
                for (int a = 0; a < 16; a++) {
                    int r = a * 8 + b;
                    acc0 = fmaf(xl0[a], Cs[r * CPAD + el] + sB3[r], acc0);
                }
                float acc1 = 0.f;
#pragma unroll
                for (int a = 0; a < 4; a++) {
                    int r = 168 + a * 8 + b;
                    acc1 = fmaf(ul1[a], Cs[r * CPAD + el] + sB3[r], acc1);
                }
                int bg = HALF * 8 + b;
                float val = NORM * fmaf(sh.x, acc0, I3 * acc1);
                if (ok) atomicAdd(&g_agg[(size_t)d * 28 + bg], p * val);
            }
            if (h < 2) {
                int j = h;
                float c01 = 0.f;
#pragma unroll
                for (int a = 0; a < 16; a++) {
                    int r = 128 + a * 2 + j;
                    c01 = fmaf(xl0[a], Cs[r * CPAD + el] + sB3[r], c01);
                }
                float dx = 0.f, dy = 0.f, dz = 0.f;
#pragma unroll
                for (int a = 0; a < 4; a++) {
                    int r = 160 + a * 2 + j;
                    float w = Cs[r * CPAD + el] + sB3[r];
                    dx = fmaf(g_eg[(size_t)(20 + a * 3 + 0) * E + ee], w, dx);
                    dy = fmaf(g_eg[(size_t)(20 + a * 3 + 1) * E + ee], w, dy);
                    dz = fmaf(g_eg[(size_t)(20 + a * 3 + 2) * E + ee], w, dz);
                }
                int jg = HALF * 2 + j;
                if (ok) {
                    atomicAdd(&g_agg[(size_t)d * 28 + 16 + jg * 3 + 0],
                              p * (NORM * (sh.y * c01 + sh.x * dx)));
                    atomicAdd(&g_agg[(size_t)d * 28 + 16 + jg * 3 + 1],
                              p * (NORM * (sh.z * c01 + sh.x * dy)));
                    atomicAdd(&g_agg[(size_t)d * 28 + 16 + jg * 3 + 2],
                              p * (NORM * (sh.w * c01 + sh.x * dz)));
                }
            }
            if (HALF == 0 && h == 0 && ok) atomicAdd(&g_z[d], p);
        }
        __syncthreads();
    }
}

// ---------------------------------------------------------------------------
__global__ void node_out_kernel(const float* __restrict__ na,
                                const float* __restrict__ Wo0,
                                const float* __restrict__ Wo1,
                                float* __restrict__ out, int N) {
    __shared__ float sW0[512], sW1[32];
    int tid = threadIdx.x;
    for (int i = tid; i < 512; i += blockDim.x) sW0[i] = Wo0[i];
    for (int i = tid; i < 32;  i += blockDim.x) sW1[i] = Wo1[i];
    __syncthreads();

    int n = blockIdx.x * blockDim.x + tid;
    if (n >= N) return;
    float z = g_z[n];
    float zi = z > 0.f ? 1.f / z : 0.f;
    float ag[28];
#pragma unroll
    for (int j = 0; j < 28; j++) ag[j] = g_agg[(size_t)n * 28 + j] * zi;

#pragma unroll
    for (int o = 0; o < 32; o++) {
        float s = 0.f;
#pragma unroll
        for (int a = 0; a < 16; a++) s = fmaf(ag[a], sW0[a * 32 + o], s);
        out[(size_t)n * 56 + o] = fmaf(s, 0.25f, na[(size_t)n * 56 + o]);
    }
#pragma unroll
    for (int o = 0; o < 8; o++)
#pragma unroll
        for (int c = 0; c < 3; c++) {
            float s = 0.f;
#pragma unroll
            for (int a = 0; a < 4; a++) s = fmaf(ag[16 + a * 3 + c], sW1[a * 8 + o], s);
            out[(size_t)n * 56 + 32 + o * 3 + c] =
                fmaf(s, 0.5f, na[(size_t)n * 56 + 32 + o * 3 + c]);
        }
}

// ---------------------------------------------------------------------------
extern "C" void kernel_launch(void* const* d_in, const int* in_sizes, int n_in,
                              void* d_out, int out_size) {
    const float* node_attr  = (const float*)d_in[0];
    const float* edge_attr  = (const float*)d_in[1];
    const float* edge_sh    = (const float*)d_in[2];
    const int*   edge_index = (const int*)  d_in[3];
    const float* W_in0  = (const float*)d_in[4];
    const float* W_in1  = (const float*)d_in[5];
    const float* Wq0    = (const float*)d_in[6];
    const float* Wq1    = (const float*)d_in[7];
    const float* Wd0    = (const float*)d_in[8];
    const float* Wd1    = (const float*)d_in[9];
    const float* W_out0 = (const float*)d_in[10];
    const float* W_out1 = (const float*)d_in[11];
    const float* fcW1 = (const float*)d_in[12];
    const float* fcb1 = (const float*)d_in[13];
    const float* fcW2 = (const float*)d_in[14];
    const float* fcb2 = (const float*)d_in[15];
    const float* fcW3 = (const float*)d_in[16];
    const float* fcb3 = (const float*)d_in[17];
    const float* fkW1 = (const float*)d_in[18];
    const float* fkb1 = (const float*)d_in[19];
    const float* fkW2 = (const float*)d_in[20];
    const float* fkb2 = (const float*)d_in[21];
    const float* fkW3 = (const float*)d_in[22];
    const float* fkb3 = (const float*)d_in[23];
    float* out = (float*)d_out;

    int N = in_sizes[0] / 56;
    int E = in_sizes[2] / 4;

    const int FRONT_SMEM = FT_FLOATS * (int)sizeof(float);  // 153088 B
    const int L3_SMEM    = L3_FLOATS * (int)sizeof(float);  // 210816 B

    cudaFuncSetAttribute(front_kernel,
                         cudaFuncAttributeMaxDynamicSharedMemorySize, FRONT_SMEM);
    cudaFuncSetAttribute(l3k_kernel,
                         cudaFuncAttributeMaxDynamicSharedMemorySize, L3_SMEM);
    cudaFuncSetAttribute(l3v_kernel<0>,
                         cudaFuncAttributeMaxDynamicSharedMemorySize, L3_SMEM);
    cudaFuncSetAttribute(l3v_kernel<1>,
                         cudaFuncAttributeMaxDynamicSharedMemorySize, L3_SMEM);

    int ft_tiles = (E + FT_TE - 1) / FT_TE;
    int l3_tiles = (E + TE - 1) / TE;

    node_prep_kernel<<<(N + 127) / 128, 128>>>(node_attr, W_in0, W_in1, Wq0, Wq1,
                                               Wd0, Wd1, N);
    front_kernel<<<NSM, 512, FRONT_SMEM>>>(edge_attr, edge_sh, edge_index,
                                           fcW1, fcb1, fcW2, fcb2,
                                           fkW1, fkb1, fkW2, fkb2, E, ft_tiles);
    l3k_kernel<<<NSM, L3_NT, L3_SMEM>>>(edge_index, edge_sh, fkW3, fkb3,
                                        E, l3_tiles);
    l3v_kernel<0><<<NSM, L3_NT, L3_SMEM>>>(edge_index, edge_sh, fcW3, fcb3,
                                           E, l3_tiles);
    l3v_kernel<1><<<NSM, L3_NT, L3_SMEM>>>(edge_index, edge_sh, fcW3, fcb3,
                                           E, l3_tiles);
    node_out_kernel<<<(N + 127) / 128, 128>>>(node_attr, W_out0, W_out1, out, N);
}